// round 1
// baseline (speedup 1.0000x reference)
#include <cuda_runtime.h>
#include <math.h>
#include <stdint.h>

#define NN 50000
#define EE 800000
#define DD 128
#define TDIM 32
#define EDIM 160
#define EPSI 0.1f
#define GAMMA_C 0.1f
#define INV_SQRT_D 0.08838834764831843f

// ---------------- scratch (static device allocations, allowed) ----------------
__device__ float    g_h[NN * DD];            // node state h            (25.6 MB)
__device__ float    g_e[(size_t)EE * DD];    // edge features e         (409.6 MB)
__device__ float    g_q[NN * DD];
__device__ float    g_k[NN * DD];
__device__ float    g_v[NN * DD];
__device__ float    g_logit[EE];             // logits, then exp values
__device__ unsigned g_segmax[NN];            // order-preserving uint keys
__device__ float    g_segsum[NN];
__device__ float    g_phi[NN * DD];
__device__ int      g_src[EE];
__device__ int      g_dst[EE];
__device__ int      g_is64;
__device__ float    g_Amat[DD * DD];         // W_anti - W_anti^T - gamma*I

// ---------------- helpers ----------------
__device__ __forceinline__ unsigned f2o(float f) {
    unsigned u = __float_as_uint(f);
    return (u & 0x80000000u) ? ~u : (u | 0x80000000u);
}
__device__ __forceinline__ float o2f(unsigned u) {
    return (u & 0x80000000u) ? __uint_as_float(u & 0x7fffffffu) : __uint_as_float(~u);
}

// ---------------- edge-index dtype detection + conversion ----------------
// If the buffer is int64, every odd 32-bit word (high half) is 0.
// If int32, 2048 consecutive src values being all-zero is impossible in practice.
__global__ void detect_kernel(const void* ei) {
    const unsigned* w = (const unsigned*)ei;
    __shared__ int nz;
    if (threadIdx.x == 0) nz = 0;
    __syncthreads();
    for (int i = threadIdx.x; i < 2048; i += 256)
        if (w[2 * i + 1] != 0u) nz = 1;
    __syncthreads();
    if (threadIdx.x == 0) g_is64 = (nz == 0) ? 1 : 0;
}

__global__ void convert_kernel(const void* ei) {
    int i = blockIdx.x * 256 + threadIdx.x;
    if (i >= EE) return;
    if (g_is64) {
        const long long* p = (const long long*)ei;
        g_src[i] = (int)p[i];
        g_dst[i] = (int)p[(size_t)EE + i];
    } else {
        const int* p = (const int*)ei;
        g_src[i] = p[i];
        g_dst[i] = p[EE + i];
    }
}

__global__ void build_A_kernel(const float* __restrict__ Wa) {
    int j = blockIdx.x, k = threadIdx.x;
    float v = Wa[j * DD + k] - Wa[k * DD + j];
    if (j == k) v -= GAMMA_C;
    g_Amat[j * DD + k] = v;
}

// ---------------- generic 128-col GEMM: C[M,128] = A[M,K] @ W[128,K]^T + bias ----------------
// MODE 0: plain bias-add store.
// MODE 1: antisymmetric update epilogue: C = Hin + eps*tanh(acc + phi + bias)  (row-local, in-place safe)
template <int MODE>
__global__ __launch_bounds__(256, 2) void gemm128(
    const float* __restrict__ A, const float* __restrict__ W,
    const float* __restrict__ bias, float* __restrict__ C,
    const float* __restrict__ phi, const float* __restrict__ Hin,
    int M, int K)
{
    __shared__ float sA[16][128];
    __shared__ float sW[16][128];
    const int t = threadIdx.x;
    const int m0 = blockIdx.x * 128;
    const int tx = t & 15;
    const int ty = t >> 4;
    const int lm = t >> 2;   // 0..63
    const int ls = t & 3;    // float4 slot

    float acc[8][8];
#pragma unroll
    for (int i = 0; i < 8; i++)
#pragma unroll
        for (int j = 0; j < 8; j++) acc[i][j] = 0.f;

    for (int kc = 0; kc < K; kc += 16) {
#pragma unroll
        for (int h = 0; h < 2; h++) {
            int m = h * 64 + lm;
            int row = m0 + m;
            float4 v = make_float4(0.f, 0.f, 0.f, 0.f);
            if (row < M) v = *(const float4*)(A + (size_t)row * K + kc + ls * 4);
            sA[ls * 4 + 0][m] = v.x; sA[ls * 4 + 1][m] = v.y;
            sA[ls * 4 + 2][m] = v.z; sA[ls * 4 + 3][m] = v.w;
        }
#pragma unroll
        for (int h = 0; h < 2; h++) {
            int n = h * 64 + lm;
            float4 v = *(const float4*)(W + (size_t)n * K + kc + ls * 4);
            sW[ls * 4 + 0][n] = v.x; sW[ls * 4 + 1][n] = v.y;
            sW[ls * 4 + 2][n] = v.z; sW[ls * 4 + 3][n] = v.w;
        }
        __syncthreads();
#pragma unroll
        for (int k = 0; k < 16; k++) {
            float4 a0 = *(const float4*)&sA[k][ty * 4];
            float4 a1 = *(const float4*)&sA[k][ty * 4 + 64];
            float4 w0 = *(const float4*)&sW[k][tx * 4];
            float4 w1 = *(const float4*)&sW[k][tx * 4 + 64];
            float av[8] = {a0.x, a0.y, a0.z, a0.w, a1.x, a1.y, a1.z, a1.w};
            float wv[8] = {w0.x, w0.y, w0.z, w0.w, w1.x, w1.y, w1.z, w1.w};
#pragma unroll
            for (int i = 0; i < 8; i++)
#pragma unroll
                for (int j = 0; j < 8; j++) acc[i][j] = fmaf(av[i], wv[j], acc[i][j]);
        }
        __syncthreads();
    }

#pragma unroll
    for (int i = 0; i < 8; i++) {
        int row = m0 + ((i < 4) ? (ty * 4 + i) : (64 + ty * 4 + (i - 4)));
        if (row >= M) continue;
#pragma unroll
        for (int j = 0; j < 8; j++) {
            int col = (j < 4) ? (tx * 4 + j) : (64 + tx * 4 + (j - 4));
            float val = acc[i][j] + bias[col];
            if (MODE == 0) {
                C[(size_t)row * 128 + col] = val;
            } else {
                val += phi[(size_t)row * 128 + col];
                C[(size_t)row * 128 + col] =
                    Hin[(size_t)row * 128 + col] + EPSI * tanhf(val);
            }
        }
    }
}

// ---------------- edge GEMM with fused time-encoding: e = [msg | cos(...)] @ We^T + be ----------------
__global__ __launch_bounds__(256, 2) void gemm_edge(
    const float* __restrict__ msg, const float* __restrict__ lastup,
    const float* __restrict__ tarr, const float* __restrict__ te_w,
    const float* __restrict__ te_b, const float* __restrict__ We,
    const float* __restrict__ be)
{
    __shared__ float sA[16][128];
    __shared__ float sW[16][128];
    __shared__ float s_relt[128];
    const int t = threadIdx.x;
    const int m0 = blockIdx.x * 128;   // 6250 blocks * 128 = EE exactly
    const int tx = t & 15;
    const int ty = t >> 4;
    const int lm = t >> 2;
    const int ls = t & 3;

    if (t < 128) {
        int row = m0 + t;
        int s = g_src[row];
        s_relt[t] = fabsf(lastup[s] - tarr[row]);
    }
    float acc[8][8];
#pragma unroll
    for (int i = 0; i < 8; i++)
#pragma unroll
        for (int j = 0; j < 8; j++) acc[i][j] = 0.f;
    __syncthreads();

    for (int chunk = 0; chunk < 10; chunk++) {
        int kc = chunk * 16;
        if (chunk < 8) {
#pragma unroll
            for (int h = 0; h < 2; h++) {
                int m = h * 64 + lm;
                int row = m0 + m;
                float4 v = *(const float4*)(msg + (size_t)row * 128 + kc + ls * 4);
                sA[ls * 4 + 0][m] = v.x; sA[ls * 4 + 1][m] = v.y;
                sA[ls * 4 + 2][m] = v.z; sA[ls * 4 + 3][m] = v.w;
            }
        } else {
#pragma unroll
            for (int h = 0; h < 2; h++) {
                int m = h * 64 + lm;
                float r = s_relt[m];
#pragma unroll
                for (int j2 = 0; j2 < 4; j2++) {
                    int kk = kc - 128 + ls * 4 + j2;
                    sA[ls * 4 + j2][m] = cosf(r * te_w[kk] + te_b[kk]);
                }
            }
        }
#pragma unroll
        for (int h = 0; h < 2; h++) {
            int n = h * 64 + lm;
            float4 v = *(const float4*)(We + (size_t)n * EDIM + kc + ls * 4);
            sW[ls * 4 + 0][n] = v.x; sW[ls * 4 + 1][n] = v.y;
            sW[ls * 4 + 2][n] = v.z; sW[ls * 4 + 3][n] = v.w;
        }
        __syncthreads();
#pragma unroll
        for (int k = 0; k < 16; k++) {
            float4 a0 = *(const float4*)&sA[k][ty * 4];
            float4 a1 = *(const float4*)&sA[k][ty * 4 + 64];
            float4 w0 = *(const float4*)&sW[k][tx * 4];
            float4 w1 = *(const float4*)&sW[k][tx * 4 + 64];
            float av[8] = {a0.x, a0.y, a0.z, a0.w, a1.x, a1.y, a1.z, a1.w};
            float wv[8] = {w0.x, w0.y, w0.z, w0.w, w1.x, w1.y, w1.z, w1.w};
#pragma unroll
            for (int i = 0; i < 8; i++)
#pragma unroll
                for (int j = 0; j < 8; j++) acc[i][j] = fmaf(av[i], wv[j], acc[i][j]);
        }
        __syncthreads();
    }

#pragma unroll
    for (int i = 0; i < 8; i++) {
        int row = m0 + ((i < 4) ? (ty * 4 + i) : (64 + ty * 4 + (i - 4)));
#pragma unroll
        for (int j = 0; j < 8; j++) {
            int col = (j < 4) ? (tx * 4 + j) : (64 + tx * 4 + (j - 4));
            g_e[(size_t)row * 128 + col] = acc[i][j] + be[col];
        }
    }
}

// ---------------- per-iteration edge kernels ----------------
__global__ void init_kernel() {
    int i = blockIdx.x * 256 + threadIdx.x;
    if (i < NN * DD) g_phi[i] = 0.f;
    if (i < NN) { g_segmax[i] = 0u; g_segsum[i] = 0.f; }
}

// warp per edge: logits = dot(q[dst], k[src]+e) * inv_sqrt_d; atomicMax into seg_max
__global__ void logits_kernel() {
    int gtid = blockIdx.x * 256 + threadIdx.x;
    int e = gtid >> 5;
    int lane = gtid & 31;
    if (e >= EE) return;
    int s = g_src[e], d = g_dst[e];
    float4 qv = *(const float4*)(g_q + (size_t)d * 128 + lane * 4);
    float4 kv = *(const float4*)(g_k + (size_t)s * 128 + lane * 4);
    float4 ev = *(const float4*)(g_e + (size_t)e * 128 + lane * 4);
    float dot = qv.x * (kv.x + ev.x) + qv.y * (kv.y + ev.y) +
                qv.z * (kv.z + ev.z) + qv.w * (kv.w + ev.w);
#pragma unroll
    for (int o = 16; o > 0; o >>= 1) dot += __shfl_xor_sync(0xffffffffu, dot, o);
    if (lane == 0) {
        float lg = dot * INV_SQRT_D;
        g_logit[e] = lg;
        atomicMax(&g_segmax[d], f2o(lg));
    }
}

__global__ void expsum_kernel() {
    int i = blockIdx.x * 256 + threadIdx.x;
    if (i >= EE) return;
    int d = g_dst[i];
    float m = o2f(g_segmax[d]);
    float ex = expf(g_logit[i] - m);
    g_logit[i] = ex;
    atomicAdd(&g_segsum[d], ex);
}

// warp per edge: phi[dst] += (v[src]+e) * alpha  via vectorized global reduction
__global__ void scatter_kernel() {
    int gtid = blockIdx.x * 256 + threadIdx.x;
    int e = gtid >> 5;
    int lane = gtid & 31;
    if (e >= EE) return;
    int s = g_src[e], d = g_dst[e];
    float alpha = g_logit[e] / g_segsum[d];
    float4 vv = *(const float4*)(g_v + (size_t)s * 128 + lane * 4);
    float4 ev = *(const float4*)(g_e + (size_t)e * 128 + lane * 4);
    float x0 = (vv.x + ev.x) * alpha;
    float x1 = (vv.y + ev.y) * alpha;
    float x2 = (vv.z + ev.z) * alpha;
    float x3 = (vv.w + ev.w) * alpha;
    float* p = g_phi + (size_t)d * 128 + lane * 4;
    asm volatile("red.global.add.v4.f32 [%0], {%1,%2,%3,%4};"
                 :: "l"(p), "f"(x0), "f"(x1), "f"(x2), "f"(x3) : "memory");
}

// ---------------- launch ----------------
extern "C" void kernel_launch(void* const* d_in, const int* in_sizes, int n_in,
                              void* d_out, int out_size)
{
    const float* x      = (const float*)d_in[0];
    const float* lastup = (const float*)d_in[1];
    const float* tarr   = (const float*)d_in[2];
    const float* msg    = (const float*)d_in[3];
    const void*  ei     = d_in[4];
    const float* enc_W  = (const float*)d_in[5];
    const float* enc_b  = (const float*)d_in[6];
    const float* te_w   = (const float*)d_in[7];
    const float* te_b   = (const float*)d_in[8];
    const float* Wq     = (const float*)d_in[9];
    const float* bq     = (const float*)d_in[10];
    const float* Wk     = (const float*)d_in[11];
    const float* bk     = (const float*)d_in[12];
    const float* Wv     = (const float*)d_in[13];
    const float* bv     = (const float*)d_in[14];
    const float* We     = (const float*)d_in[15];
    const float* be     = (const float*)d_in[16];
    const float* Wa     = (const float*)d_in[17];
    const float* ba     = (const float*)d_in[18];
    float* out = (float*)d_out;

    float *ph, *pq, *pk, *pv, *pphi, *pA;
    cudaGetSymbolAddress((void**)&ph,   g_h);
    cudaGetSymbolAddress((void**)&pq,   g_q);
    cudaGetSymbolAddress((void**)&pk,   g_k);
    cudaGetSymbolAddress((void**)&pv,   g_v);
    cudaGetSymbolAddress((void**)&pphi, g_phi);
    cudaGetSymbolAddress((void**)&pA,   g_Amat);

    const int gemm_n_blocks = (NN + 127) / 128;   // 391
    const int edge_blocks   = EE / 128;           // 6250
    const int warp_blocks   = (EE * 32 + 255) / 256; // 100000

    detect_kernel<<<1, 256>>>(ei);
    convert_kernel<<<(EE + 255) / 256, 256>>>(ei);
    build_A_kernel<<<DD, DD>>>(Wa);

    // h0 = x @ enc_W^T + enc_b
    gemm128<0><<<gemm_n_blocks, 256>>>(x, enc_W, enc_b, ph, nullptr, nullptr, NN, 256);
    // e = [msg | time_enc] @ We^T + be  (iteration-invariant)
    gemm_edge<<<edge_blocks, 256>>>(msg, lastup, tarr, te_w, te_b, We, be);

    for (int it = 0; it < 3; it++) {
        gemm128<0><<<gemm_n_blocks, 256>>>(ph, Wq, bq, pq, nullptr, nullptr, NN, 128);
        gemm128<0><<<gemm_n_blocks, 256>>>(ph, Wk, bk, pk, nullptr, nullptr, NN, 128);
        gemm128<0><<<gemm_n_blocks, 256>>>(ph, Wv, bv, pv, nullptr, nullptr, NN, 128);
        init_kernel<<<(NN * DD + 255) / 256, 256>>>();
        logits_kernel<<<warp_blocks, 256>>>();
        expsum_kernel<<<(EE + 255) / 256, 256>>>();
        scatter_kernel<<<warp_blocks, 256>>>();
        // h = h + eps * tanh(h @ A^T + phi + b_anti)   (in-place safe; last iter -> d_out)
        gemm128<1><<<gemm_n_blocks, 256>>>(ph, pA, ba, (it == 2) ? out : ph,
                                           pphi, ph, NN, 128);
    }
}